// round 16
// baseline (speedup 1.0000x reference)
#include <cuda_runtime.h>

#define Bq 8
#define Cq 64
#define CIq 32
#define Nq 2304          // 48*48
#define NP1 2305
#define TILES 36         // 2304/64
#define NTILE (Bq*TILES) // 288
#define NCH 72           // chunks per batch
#define CHSZ 32
#define GRID 148
#define NTHR 512
#define NBUCK 2048

// ---------------- scratch (__device__ globals; no allocations) ----------------
__device__ float s_a[Bq*Nq];
__device__ float s_gx[Bq*Nq*CIq];          // [b][n][i]
__device__ float s_keys[Bq*Nq];            // sorted b ascending
__device__ int   s_perm[Bq*Nq];
__device__ int   s_kstar[Bq*Nq];
__device__ float s_ctg[Bq*NCH*CIq];        // chunk totals (g)
__device__ float s_ctbg[Bq*NCH*CIq];       // chunk totals (b*g)
__device__ float s_Sg[Bq*NP1*CIq];         // inclusive suffix sums
__device__ float s_Sbg[Bq*NP1*CIq];
__device__ float s_wy[Bq*Cq*Nq];           // pre-BN output
__device__ unsigned long long g_sum[Cq];   // Q32.32 fixed-point BN accumulators
__device__ unsigned long long g_sqs[Cq];

// grid barrier state
__device__ unsigned g_bar = 0;
__device__ volatile unsigned g_gen = 0;

__device__ __forceinline__ void gsync() {
    __syncthreads();
    if (threadIdx.x == 0) {
        __threadfence();
        unsigned gen = g_gen;
        if (atomicAdd(&g_bar, 1u) == gridDim.x - 1) {
            g_bar = 0;
            __threadfence();
            g_gen = gen + 1;
        } else {
            while (g_gen == gen) { __nanosleep(32); }
        }
        __threadfence();
    }
    __syncthreads();
}

__global__ __launch_bounds__(NTHR, 1) void fused_nonlocal(
    const float* __restrict__ x,
    const float* __restrict__ g_w,  const float* __restrict__ g_b,
    const float* __restrict__ th_w, const float* __restrict__ th_b,
    const float* __restrict__ ph_w, const float* __restrict__ ph_b,
    const float* __restrict__ cp_wt, const float* __restrict__ cp_wp,
    const float* __restrict__ W_w,  const float* __restrict__ W_b,
    const float* __restrict__ bn_g, const float* __restrict__ bn_b,
    float* __restrict__ out)
{
    __shared__ __align__(16) unsigned char SM[43808];
    int t = threadIdx.x;
    int w = t >> 5, lane = t & 31;

    // ======= P1: blocks 0-7: b-scores + bucket sort ; blocks 8-147: gx + a ====
    if (blockIdx.x < Bq) {
        float* kb    = (float*)SM;                 // 2304 floats
        int*   blist = (int*)(SM + 9216);          // 2304 ints
        int*   off   = (int*)(SM + 18432);         // 2049 ints
        int*   cnt   = (int*)(SM + 26640);         // 2048 ints
        int*   aux   = (int*)(SM + 34832);         // 16 ints
        float* auxf  = (float*)(SM + 34912);       // 34 floats
        float* wbs   = (float*)(SM + 35200);       // 64 floats
        float* cbp   = (float*)(SM + 35456);       // 1 float

        int b = blockIdx.x;

        if (t < 64) {
            float sb = 0.f;
            #pragma unroll
            for (int i = 0; i < CIq; i++)
                sb = fmaf(cp_wp[i], ph_w[i*Cq + t], sb);
            wbs[t] = sb;
        } else if (t == 64) {
            float cb = 0.f;
            #pragma unroll
            for (int i = 0; i < CIq; i++) cb = fmaf(cp_wp[i], ph_b[i], cb);
            cbp[0] = cb;
        }
        for (int idx = t; idx < NBUCK + 1; idx += NTHR) off[idx] = 0;
        __syncthreads();

        {
            float cb = cbp[0];
            float accb[5];
            #pragma unroll
            for (int q = 0; q < 5; q++) accb[q] = cb;
            const float* xb = x + b*Cq*Nq;
            for (int c = 0; c < Cq; c++) {
                float wv = wbs[c];
                const float* xc = xb + c*Nq;
                accb[0] = fmaf(wv, xc[t], accb[0]);
                accb[1] = fmaf(wv, xc[512 + t], accb[1]);
                accb[2] = fmaf(wv, xc[1024 + t], accb[2]);
                accb[3] = fmaf(wv, xc[1536 + t], accb[3]);
                if (t < 256) accb[4] = fmaf(wv, xc[2048 + t], accb[4]);
            }
            kb[t]        = accb[0];
            kb[512 + t]  = accb[1];
            kb[1024 + t] = accb[2];
            kb[1536 + t] = accb[3];
            if (t < 256) kb[2048 + t] = accb[4];
        }
        __syncthreads();

        // ---------- bucket sort over kb (deterministic) ----------
        float lmin = 3.4e38f, lmax = -3.4e38f;
        for (int m = t; m < Nq; m += NTHR) {
            float v = kb[m];
            lmin = fminf(lmin, v); lmax = fmaxf(lmax, v);
        }
        #pragma unroll
        for (int d = 16; d > 0; d >>= 1) {
            lmin = fminf(lmin, __shfl_xor_sync(0xffffffffu, lmin, d));
            lmax = fmaxf(lmax, __shfl_xor_sync(0xffffffffu, lmax, d));
        }
        if (lane == 0) { auxf[w] = lmin; auxf[16 + w] = lmax; }
        __syncthreads();
        if (t == 0) {
            float mn = auxf[0], mx = auxf[16];
            for (int k = 1; k < 16; k++) {
                mn = fminf(mn, auxf[k]); mx = fmaxf(mx, auxf[16 + k]);
            }
            auxf[32] = mn;
            auxf[33] = (mx > mn) ? ((float)(NBUCK - 1) / (mx - mn)) : 0.f;
        }
        __syncthreads();
        float minv = auxf[32], scale = auxf[33];

        for (int m = t; m < Nq; m += NTHR) {
            int bk = (int)((kb[m] - minv) * scale);
            bk = max(0, min(NBUCK - 1, bk));
            atomicAdd(&off[bk], 1);
        }
        __syncthreads();

        int base = t * 4;
        int h0 = off[base], h1 = off[base+1], h2 = off[base+2], h3 = off[base+3];
        int tsum = h0 + h1 + h2 + h3;
        int inc = tsum;
        #pragma unroll
        for (int d = 1; d < 32; d <<= 1) {
            int v = __shfl_up_sync(0xffffffffu, inc, d);
            if (lane >= d) inc += v;
        }
        if (lane == 31) aux[w] = inc;
        __syncthreads();
        if (t == 0) {
            int acc = 0;
            for (int k = 0; k < 16; k++) { int v = aux[k]; aux[k] = acc; acc += v; }
        }
        __syncthreads();
        int excl = aux[w] + (inc - tsum);
        off[base]     = excl;
        off[base + 1] = excl + h0;
        off[base + 2] = excl + h0 + h1;
        off[base + 3] = excl + h0 + h1 + h2;
        cnt[base] = excl; cnt[base+1] = excl + h0;
        cnt[base+2] = excl + h0 + h1; cnt[base+3] = excl + h0 + h1 + h2;
        if (t == 0) off[NBUCK] = Nq;
        __syncthreads();

        for (int m = t; m < Nq; m += NTHR) {
            int bk = (int)((kb[m] - minv) * scale);
            bk = max(0, min(NBUCK - 1, bk));
            int slot = atomicAdd(&cnt[bk], 1);
            blist[slot] = m;
        }
        __syncthreads();

        for (int m = t; m < Nq; m += NTHR) {
            float v = kb[m];
            int bk = (int)((v - minv) * scale);
            bk = max(0, min(NBUCK - 1, bk));
            int lo = off[bk], hi = off[bk + 1];
            int r = lo;
            for (int j = lo; j < hi; j++) {
                int jm = blist[j];
                float vj = kb[jm];
                r += (vj < v) || (vj == v && jm < m);
            }
            s_keys[b*Nq + r] = v;
            s_perm[b*Nq + r] = m;
        }
    } else {
        // ---------- gx projection + a scores (pair of tiles per iteration) ----
        float* xs  = (float*)SM;                      // [2][64*68]
        float* gws = (float*)(SM + 34816);            // 32*65
        float* was = (float*)(SM + 43136);            // 64
        float* cst = (float*)(SM + 43648);            // 1
        float* gbs = (float*)(SM + 43664);            // 32

        if (blockIdx.x == 8 && t < Cq) {              // zero BN accumulators
            g_sum[t] = 0ull;
            g_sqs[t] = 0ull;
        }

        if (t < 64) {
            float sa = 0.f;
            #pragma unroll
            for (int i = 0; i < CIq; i++)
                sa = fmaf(cp_wt[i], th_w[i*Cq + t], sa);
            was[t] = sa;
        } else if (t == 64) {
            float ca = 0.f;
            #pragma unroll
            for (int i = 0; i < CIq; i++) ca = fmaf(cp_wt[i], th_b[i], ca);
            cst[0] = ca;
        }
        if (t >= 128 && t < 160) gbs[t - 128] = g_b[t - 128];
        for (int idx = t; idx < CIq*Cq; idx += NTHR)
            gws[(idx >> 6)*65 + (idx & 63)] = g_w[idx];
        __syncthreads();

        int half = t >> 8, tt = t & 255;
        int i = tt & 31, pg = tt >> 5;
        float* xsh = xs + half*(64*68);
        float gb_i = gbs[i];

        for (int pair = blockIdx.x - 8; pair < NTILE/2; pair += GRID - 8) {
            int tile = pair*2 + half;
            int b = tile / TILES, n0 = (tile % TILES)*64;
            float4* xs4 = (float4*)xsh;
            const float4* xg = (const float4*)x;
            for (int idx = tt; idx < Cq*16; idx += 256) {
                int c = idx >> 4, q = idx & 15;
                xs4[c*17 + q] = xg[(((b*Cq + c)*Nq + n0) >> 2) + q];
            }
            __syncthreads();

            float acc[8];
            #pragma unroll
            for (int p = 0; p < 8; p++) acc[p] = gb_i;
            #pragma unroll
            for (int c = 0; c < Cq; c++) {
                float ww = gws[i*65 + c];
                float4 xa = *(const float4*)&xsh[c*68 + pg*8];
                float4 xb = *(const float4*)&xsh[c*68 + pg*8 + 4];
                acc[0] = fmaf(ww, xa.x, acc[0]); acc[1] = fmaf(ww, xa.y, acc[1]);
                acc[2] = fmaf(ww, xa.z, acc[2]); acc[3] = fmaf(ww, xa.w, acc[3]);
                acc[4] = fmaf(ww, xb.x, acc[4]); acc[5] = fmaf(ww, xb.y, acc[5]);
                acc[6] = fmaf(ww, xb.z, acc[6]); acc[7] = fmaf(ww, xb.w, acc[7]);
            }
            #pragma unroll
            for (int p = 0; p < 8; p++)
                s_gx[(b*Nq + n0 + pg*8 + p)*CIq + i] = acc[p];

            if (tt < 64) {
                float aa = cst[0];
                #pragma unroll
                for (int c = 0; c < Cq; c++)
                    aa = fmaf(was[c], xsh[c*68 + tt], aa);
                s_a[b*Nq + n0 + tt] = aa;
            }
            __syncthreads();
        }
    }
    gsync();

    // ===== P3: blocks 0-143 pre-stage P4 gxs/pm/ks (P1-dependent only);
    //           blocks 0-71 also run chunk totals + fast k* searches ===========
    {
        float* gxs = (float*)SM;                   // [4][32][32] = 16384B
        float* ks  = (float*)(SM + 16384);         // [4][32] = 512B
        int*   pm  = (int*)(SM + 16896);           // [4][32] = 512B

        if (blockIdx.x < 144) {
            int b4 = blockIdx.x / 18;
            int cg0 = (blockIdx.x % 18) * 4;
            if (t < 128) {
                pm[t] = s_perm[b4*Nq + cg0*CHSZ + t];
                ks[t] = s_keys[b4*Nq + cg0*CHSZ + t];
            }
            __syncthreads();
            for (int idx = t; idx < 4*32*32; idx += NTHR) {
                int row = idx >> 5, i = idx & 31;
                gxs[idx] = s_gx[(b4*Nq + pm[row])*CIq + i];
            }
        }

        if (blockIdx.x < 72) {
            int gwid = blockIdx.x * 16 + w;        // 0..1151
            if (gwid < Bq*NCH) {
                // chunk totals
                int b = gwid / NCH, ch = gwid % NCH;
                int k0 = ch * CHSZ;
                int   mlane = s_perm[b*Nq + k0 + lane];
                float klane = s_keys[b*Nq + k0 + lane];
                const float* gxb = s_gx + b*Nq*CIq;
                float ag = 0.f, abg = 0.f;
                #pragma unroll 8
                for (int j = 0; j < 32; j++) {
                    int   mm = __shfl_sync(0xffffffffu, mlane, j);
                    float kk = __shfl_sync(0xffffffffu, klane, j);
                    float gg = gxb[mm*CIq + lane];
                    ag += gg;
                    abg = fmaf(kk, gg, abg);
                }
                s_ctg [(b*NCH + ch)*CIq + lane] = ag;
                s_ctbg[(b*NCH + ch)*CIq + lane] = abg;
                if (blockIdx.x == 0 && w < Bq) {   // empty-suffix rows
                    s_Sg [(w*NP1 + Nq)*CIq + lane] = 0.f;
                    s_Sbg[(w*NP1 + Nq)*CIq + lane] = 0.f;
                }
            } else {
                // fast k*: coarse boundary count + bulk chunk scan
                int idx = gwid - Bq*NCH;
                int b = idx / NCH;
                int p = (idx % NCH)*32 + lane;
                float thr = -s_a[b*Nq + p];
                const float* keys = s_keys + b*Nq;
                float bnd0 = keys[lane*32 + 31];
                float bnd1 = keys[(lane + 32)*32 + 31];
                float bnd2 = (lane < 8) ? keys[(lane + 64)*32 + 31] : 3.4e38f;
                int ci = 0;
                #pragma unroll
                for (int l = 0; l < 32; l++)
                    ci += (__shfl_sync(0xffffffffu, bnd0, l) <= thr);
                #pragma unroll
                for (int l = 0; l < 32; l++)
                    ci += (__shfl_sync(0xffffffffu, bnd1, l) <= thr);
                #pragma unroll
                for (int l = 0; l < 8; l++)
                    ci += (__shfl_sync(0xffffffffu, bnd2, l) <= thr);
                int kst;
                if (ci >= NCH) {
                    kst = Nq;
                } else {
                    const float4* ck = (const float4*)(keys + ci*CHSZ);
                    int c2 = 0;
                    #pragma unroll
                    for (int q = 0; q < 8; q++) {
                        float4 v = ck[q];
                        c2 += (v.x <= thr) + (v.y <= thr) + (v.z <= thr) + (v.w <= thr);
                    }
                    kst = ci*CHSZ + c2;
                }
                s_kstar[b*Nq + p] = kst;
            }
        }
    }
    gsync();

    // ===== P4: suffix rows; gxs/pm/ks already resident; stage tg/tbg only =====
    if (blockIdx.x < 144) {
        float* gxs = (float*)SM;                   // persisted
        float* ks  = (float*)(SM + 16384);         // persisted
        float* tg  = (float*)(SM + 17408);         // [73][32] = 9344B
        float* tbg = (float*)(SM + 26752);         // [73][32]

        int b = blockIdx.x / 18;
        int cg0 = (blockIdx.x % 18) * 4;

        for (int idx = t; idx < 73*32; idx += NTHR) {
            float vg = 0.f, vbg = 0.f;
            if (idx < NCH*CIq) {
                vg  = s_ctg [b*NCH*CIq + idx];
                vbg = s_ctbg[b*NCH*CIq + idx];
            }
            tg[idx] = vg; tbg[idx] = vbg;
        }
        __syncthreads();

        if (t < 64) {
            float* p = (t >> 5) ? tbg : tg;
            int i = t & 31;
            float run = 0.f;
            for (int c = NCH - 1; c >= 0; c--) {
                run += p[c*32 + i];
                p[c*32 + i] = run;
            }
        }
        __syncthreads();

        {
            int q = w >> 2, hc = w & 3;
            int ch = cg0 + q;
            float rg  = tg [(ch + 1)*32 + lane];   // exclusive carry
            float rbg = tbg[(ch + 1)*32 + lane];
            int k0 = ch * CHSZ;
            int jstart = hc * 8;
            #pragma unroll
            for (int j = 31; j >= 0; j--) {
                if (j >= jstart) {
                    float gg = gxs[(q*32 + j)*32 + lane];
                    float kk = ks[q*32 + j];
                    rg += gg;
                    rbg = fmaf(kk, gg, rbg);
                    if (j < jstart + 8) {
                        s_Sg [(b*NP1 + k0 + j)*CIq + lane] = rg;
                        s_Sbg[(b*NP1 + k0 + j)*CIq + lane] = rbg;
                    }
                }
            }
        }
    }
    gsync();

    // ===== P5: y lookup + W projection + BN atomics (pair of tiles/block) =====
    if (blockIdx.x < NTILE/2) {
        float* ws   = (float*)SM;                     // 64*33 = 8448B
        float* ys   = (float*)(SM + 8448);            // [2][64*36] = 18432B
        float* a_sm = (float*)(SM + 26880);           // [2][64]
        int*   k_sm = (int*)(SM + 27392);             // [2][64]
        float* psum = (float*)(SM + 27904);           // [2][4*64]
        float* psq  = (float*)(SM + 29952);           // [2][4*64]

        for (int idx = t; idx < Cq*CIq; idx += NTHR)
            ws[(idx >> 5)*33 + (idx & 31)] = W_w[idx];

        int half = t >> 8, tt = t & 255;
        float* ysh = ys + half*(64*36);
        int tile = blockIdx.x*2 + half;
        int b = tile / TILES, n0 = (tile % TILES)*64;

        if (tt < 64) {
            a_sm[half*64 + tt] = s_a[b*Nq + n0 + tt];
            k_sm[half*64 + tt] = s_kstar[b*Nq + n0 + tt];
        }
        __syncthreads();

        {
            int i = tt & 31, pg = tt >> 5;
            #pragma unroll
            for (int p = 0; p < 8; p++) {
                int pos = pg*8 + p;
                int k = k_sm[half*64 + pos];
                float sg  = s_Sg [(b*NP1 + k)*CIq + i];
                float sbg = s_Sbg[(b*NP1 + k)*CIq + i];
                ysh[pos*36 + i] = fmaf(a_sm[half*64 + pos], sg, sbg) * (1.0f / (float)Nq);
            }
        }
        __syncthreads();

        {
            int c = tt & 63, sub = tt >> 6;
            float wreg[CIq];
            #pragma unroll
            for (int i = 0; i < CIq; i++) wreg[i] = ws[c*33 + i];
            float wbc = W_b[c];
            float ls = 0.f, ls2 = 0.f;
            float* wyrow = s_wy + (b*Cq + c)*Nq + n0 + sub*16;
            #pragma unroll
            for (int q4 = 0; q4 < 4; q4++) {
                float av[4];
                #pragma unroll
                for (int u = 0; u < 4; u++) {
                    int pos = sub*16 + q4*4 + u;
                    const float4* yv = (const float4*)&ysh[pos*36];
                    float acc = 0.f;
                    #pragma unroll
                    for (int i4 = 0; i4 < CIq/4; i4++) {
                        float4 v = yv[i4];
                        acc = fmaf(wreg[i4*4+0], v.x, acc);
                        acc = fmaf(wreg[i4*4+1], v.y, acc);
                        acc = fmaf(wreg[i4*4+2], v.z, acc);
                        acc = fmaf(wreg[i4*4+3], v.w, acc);
                    }
                    av[u] = acc;
                    ls += acc; ls2 = fmaf(acc, acc, ls2);
                }
                float4 o;
                o.x = av[0] + wbc; o.y = av[1] + wbc;
                o.z = av[2] + wbc; o.w = av[3] + wbc;
                *(float4*)(wyrow + q4*4) = o;
            }
            psum[half*256 + sub*64 + c] = ls;
            psq [half*256 + sub*64 + c] = ls2;
        }
        __syncthreads();

        if (tt < 64) {
            int o = half*256;
            float s  = psum[o+tt] + psum[o+64+tt] + psum[o+128+tt] + psum[o+192+tt];
            float s2 = psq[o+tt]  + psq[o+64+tt]  + psq[o+128+tt]  + psq[o+192+tt];
            // Q32.32 fixed-point accumulation: deterministic (integer add)
            long long qs  = __double2ll_rn((double)s  * 4294967296.0);
            long long qs2 = __double2ll_rn((double)s2 * 4294967296.0);
            atomicAdd(&g_sum[tt], (unsigned long long)qs);
            atomicAdd(&g_sqs[tt], (unsigned long long)qs2);
        }
    }
    gsync();

    // ========== P6: BN stats from fixed-point accumulators + final ==========
    {
        float* scale = (float*)SM;            // 64
        float* shift = (float*)(SM + 256);    // 64

        if (t < 64) {
            double ss = (double)(long long)g_sum[t] * (1.0 / 4294967296.0);
            double qq = (double)(long long)g_sqs[t] * (1.0 / 4294967296.0);
            const double M = (double)(Bq * Nq);
            double mv = ss / M;
            double var = qq / M - mv*mv;
            float mean = W_b[t] + (float)mv;
            float sc = bn_g[t] * rsqrtf((float)var + 1e-5f);
            scale[t] = sc;
            shift[t] = bn_b[t] - mean*sc;
        }
        __syncthreads();

        const int TOT4 = Bq*Cq*Nq/4;
        const float4* wy4 = (const float4*)s_wy;
        const float4* x4  = (const float4*)x;
        float4* o4 = (float4*)out;
        for (int i4 = blockIdx.x*NTHR + t; i4 < TOT4; i4 += GRID*NTHR) {
            int c2 = (i4 / (Nq/4)) & 63;
            float sc = scale[c2], sh = shift[c2];
            float4 ww = wy4[i4];
            float4 xv = x4[i4];
            float4 o;
            o.x = fmaf(ww.x, sc, sh) + xv.x;
            o.y = fmaf(ww.y, sc, sh) + xv.y;
            o.z = fmaf(ww.z, sc, sh) + xv.z;
            o.w = fmaf(ww.w, sc, sh) + xv.w;
            o4[i4] = o;
        }
    }
}

// ---------------- launch ----------------
extern "C" void kernel_launch(void* const* d_in, const int* in_sizes, int n_in,
                              void* d_out, int out_size) {
    const float* x     = (const float*)d_in[0];
    const float* g_w   = (const float*)d_in[1];
    const float* g_b   = (const float*)d_in[2];
    const float* th_w  = (const float*)d_in[3];
    const float* th_b  = (const float*)d_in[4];
    const float* ph_w  = (const float*)d_in[5];
    const float* ph_b  = (const float*)d_in[6];
    const float* cp_wt = (const float*)d_in[7];
    const float* cp_wp = (const float*)d_in[8];
    const float* W_w   = (const float*)d_in[9];
    const float* W_b   = (const float*)d_in[10];
    const float* bn_g  = (const float*)d_in[11];
    const float* bn_b  = (const float*)d_in[12];
    float* out = (float*)d_out;

    fused_nonlocal<<<GRID, NTHR>>>(x, g_w, g_b, th_w, th_b, ph_w, ph_b,
                                   cp_wt, cp_wp, W_w, W_b, bn_g, bn_b, out);
}

// round 17
// speedup vs baseline: 1.0564x; 1.0564x over previous
#include <cuda_runtime.h>

#define Bq 8
#define Cq 64
#define CIq 32
#define Nq 2304          // 48*48
#define NP1 2305
#define TILES 36         // 2304/64
#define NTILE (Bq*TILES) // 288
#define NCH 72           // chunks per batch
#define CHSZ 32
#define GRID 148
#define NTHR 512
#define NBUCK 2048

// ---------------- scratch (__device__ globals; no allocations) ----------------
__device__ float s_a[Bq*Nq];
__device__ float s_gx[Bq*Nq*CIq];          // [b][n][i]
__device__ float s_keys[Bq*Nq];            // sorted b ascending
__device__ int   s_perm[Bq*Nq];
__device__ int   s_kstar[Bq*Nq];
__device__ float s_ctg[Bq*NCH*CIq];        // chunk totals (g)
__device__ float s_ctbg[Bq*NCH*CIq];       // chunk totals (b*g)
__device__ float s_Sg[Bq*NP1*CIq];         // inclusive suffix sums
__device__ float s_Sbg[Bq*NP1*CIq];
__device__ float s_wy[Bq*Cq*Nq];           // pre-BN output
__device__ float s_part[NTILE*Cq*2];       // per-tile (sum, sumsq)

// grid barrier state
__device__ unsigned g_bar = 0;
__device__ volatile unsigned g_gen = 0;

__device__ __forceinline__ void gsync() {
    __syncthreads();
    if (threadIdx.x == 0) {
        __threadfence();
        unsigned gen = g_gen;
        if (atomicAdd(&g_bar, 1u) == gridDim.x - 1) {
            g_bar = 0;
            __threadfence();
            g_gen = gen + 1;
        } else {
            while (g_gen == gen) { __nanosleep(32); }
        }
        __threadfence();
    }
    __syncthreads();
}

__global__ __launch_bounds__(NTHR, 1) void fused_nonlocal(
    const float* __restrict__ x,
    const float* __restrict__ g_w,  const float* __restrict__ g_b,
    const float* __restrict__ th_w, const float* __restrict__ th_b,
    const float* __restrict__ ph_w, const float* __restrict__ ph_b,
    const float* __restrict__ cp_wt, const float* __restrict__ cp_wp,
    const float* __restrict__ W_w,  const float* __restrict__ W_b,
    const float* __restrict__ bn_g, const float* __restrict__ bn_b,
    float* __restrict__ out)
{
    __shared__ __align__(16) unsigned char SM[43808];
    int t = threadIdx.x;
    int w = t >> 5, lane = t & 31;

    // ======= P1: blocks 0-7: b-scores + bucket sort ; blocks 8-147: gx + a ====
    if (blockIdx.x < Bq) {
        float* kb    = (float*)SM;                 // 2304 floats
        int*   blist = (int*)(SM + 9216);          // 2304 ints
        int*   off   = (int*)(SM + 18432);         // 2049 ints
        int*   cnt   = (int*)(SM + 26640);         // 2048 ints
        int*   aux   = (int*)(SM + 34832);         // 16 ints
        float* auxf  = (float*)(SM + 34912);       // 34 floats
        float* wbs   = (float*)(SM + 35200);       // 64 floats
        float* cbp   = (float*)(SM + 35456);       // 1 float

        int b = blockIdx.x;

        if (t < 64) {
            float sb = 0.f;
            #pragma unroll
            for (int i = 0; i < CIq; i++)
                sb = fmaf(cp_wp[i], ph_w[i*Cq + t], sb);
            wbs[t] = sb;
        } else if (t == 64) {
            float cb = 0.f;
            #pragma unroll
            for (int i = 0; i < CIq; i++) cb = fmaf(cp_wp[i], ph_b[i], cb);
            cbp[0] = cb;
        }
        for (int idx = t; idx < NBUCK + 1; idx += NTHR) off[idx] = 0;
        __syncthreads();

        {
            float cb = cbp[0];
            float accb[5];
            #pragma unroll
            for (int q = 0; q < 5; q++) accb[q] = cb;
            const float* xb = x + b*Cq*Nq;
            for (int c = 0; c < Cq; c++) {
                float wv = wbs[c];
                const float* xc = xb + c*Nq;
                accb[0] = fmaf(wv, xc[t], accb[0]);
                accb[1] = fmaf(wv, xc[512 + t], accb[1]);
                accb[2] = fmaf(wv, xc[1024 + t], accb[2]);
                accb[3] = fmaf(wv, xc[1536 + t], accb[3]);
                if (t < 256) accb[4] = fmaf(wv, xc[2048 + t], accb[4]);
            }
            kb[t]        = accb[0];
            kb[512 + t]  = accb[1];
            kb[1024 + t] = accb[2];
            kb[1536 + t] = accb[3];
            if (t < 256) kb[2048 + t] = accb[4];
        }
        __syncthreads();

        // ---------- bucket sort over kb (deterministic) ----------
        float lmin = 3.4e38f, lmax = -3.4e38f;
        for (int m = t; m < Nq; m += NTHR) {
            float v = kb[m];
            lmin = fminf(lmin, v); lmax = fmaxf(lmax, v);
        }
        #pragma unroll
        for (int d = 16; d > 0; d >>= 1) {
            lmin = fminf(lmin, __shfl_xor_sync(0xffffffffu, lmin, d));
            lmax = fmaxf(lmax, __shfl_xor_sync(0xffffffffu, lmax, d));
        }
        if (lane == 0) { auxf[w] = lmin; auxf[16 + w] = lmax; }
        __syncthreads();
        if (t == 0) {
            float mn = auxf[0], mx = auxf[16];
            for (int k = 1; k < 16; k++) {
                mn = fminf(mn, auxf[k]); mx = fmaxf(mx, auxf[16 + k]);
            }
            auxf[32] = mn;
            auxf[33] = (mx > mn) ? ((float)(NBUCK - 1) / (mx - mn)) : 0.f;
        }
        __syncthreads();
        float minv = auxf[32], scale = auxf[33];

        for (int m = t; m < Nq; m += NTHR) {
            int bk = (int)((kb[m] - minv) * scale);
            bk = max(0, min(NBUCK - 1, bk));
            atomicAdd(&off[bk], 1);
        }
        __syncthreads();

        int base = t * 4;
        int h0 = off[base], h1 = off[base+1], h2 = off[base+2], h3 = off[base+3];
        int tsum = h0 + h1 + h2 + h3;
        int inc = tsum;
        #pragma unroll
        for (int d = 1; d < 32; d <<= 1) {
            int v = __shfl_up_sync(0xffffffffu, inc, d);
            if (lane >= d) inc += v;
        }
        if (lane == 31) aux[w] = inc;
        __syncthreads();
        if (t == 0) {
            int acc = 0;
            for (int k = 0; k < 16; k++) { int v = aux[k]; aux[k] = acc; acc += v; }
        }
        __syncthreads();
        int excl = aux[w] + (inc - tsum);
        off[base]     = excl;
        off[base + 1] = excl + h0;
        off[base + 2] = excl + h0 + h1;
        off[base + 3] = excl + h0 + h1 + h2;
        cnt[base] = excl; cnt[base+1] = excl + h0;
        cnt[base+2] = excl + h0 + h1; cnt[base+3] = excl + h0 + h1 + h2;
        if (t == 0) off[NBUCK] = Nq;
        __syncthreads();

        for (int m = t; m < Nq; m += NTHR) {
            int bk = (int)((kb[m] - minv) * scale);
            bk = max(0, min(NBUCK - 1, bk));
            int slot = atomicAdd(&cnt[bk], 1);
            blist[slot] = m;
        }
        __syncthreads();

        for (int m = t; m < Nq; m += NTHR) {
            float v = kb[m];
            int bk = (int)((v - minv) * scale);
            bk = max(0, min(NBUCK - 1, bk));
            int lo = off[bk], hi = off[bk + 1];
            int r = lo;
            for (int j = lo; j < hi; j++) {
                int jm = blist[j];
                float vj = kb[jm];
                r += (vj < v) || (vj == v && jm < m);
            }
            s_keys[b*Nq + r] = v;
            s_perm[b*Nq + r] = m;
        }
    } else {
        // ---------- gx projection + a scores (pair of tiles per iteration) ----
        float* xs  = (float*)SM;                      // [2][64*68]
        float* gws = (float*)(SM + 34816);            // 32*65
        float* was = (float*)(SM + 43136);            // 64
        float* cst = (float*)(SM + 43648);            // 1
        float* gbs = (float*)(SM + 43664);            // 32

        if (t < 64) {
            float sa = 0.f;
            #pragma unroll
            for (int i = 0; i < CIq; i++)
                sa = fmaf(cp_wt[i], th_w[i*Cq + t], sa);
            was[t] = sa;
        } else if (t == 64) {
            float ca = 0.f;
            #pragma unroll
            for (int i = 0; i < CIq; i++) ca = fmaf(cp_wt[i], th_b[i], ca);
            cst[0] = ca;
        }
        if (t >= 128 && t < 160) gbs[t - 128] = g_b[t - 128];
        for (int idx = t; idx < CIq*Cq; idx += NTHR)
            gws[(idx >> 6)*65 + (idx & 63)] = g_w[idx];
        __syncthreads();

        int half = t >> 8, tt = t & 255;
        int i = tt & 31, pg = tt >> 5;
        float* xsh = xs + half*(64*68);
        float gb_i = gbs[i];

        for (int pair = blockIdx.x - 8; pair < NTILE/2; pair += GRID - 8) {
            int tile = pair*2 + half;
            int b = tile / TILES, n0 = (tile % TILES)*64;
            float4* xs4 = (float4*)xsh;
            const float4* xg = (const float4*)x;
            for (int idx = tt; idx < Cq*16; idx += 256) {
                int c = idx >> 4, q = idx & 15;
                xs4[c*17 + q] = xg[(((b*Cq + c)*Nq + n0) >> 2) + q];
            }
            __syncthreads();

            float acc[8];
            #pragma unroll
            for (int p = 0; p < 8; p++) acc[p] = gb_i;
            #pragma unroll
            for (int c = 0; c < Cq; c++) {
                float ww = gws[i*65 + c];
                float4 xa = *(const float4*)&xsh[c*68 + pg*8];
                float4 xb = *(const float4*)&xsh[c*68 + pg*8 + 4];
                acc[0] = fmaf(ww, xa.x, acc[0]); acc[1] = fmaf(ww, xa.y, acc[1]);
                acc[2] = fmaf(ww, xa.z, acc[2]); acc[3] = fmaf(ww, xa.w, acc[3]);
                acc[4] = fmaf(ww, xb.x, acc[4]); acc[5] = fmaf(ww, xb.y, acc[5]);
                acc[6] = fmaf(ww, xb.z, acc[6]); acc[7] = fmaf(ww, xb.w, acc[7]);
            }
            #pragma unroll
            for (int p = 0; p < 8; p++)
                s_gx[(b*Nq + n0 + pg*8 + p)*CIq + i] = acc[p];

            if (tt < 64) {
                float aa = cst[0];
                #pragma unroll
                for (int c = 0; c < Cq; c++)
                    aa = fmaf(was[c], xsh[c*68 + tt], aa);
                s_a[b*Nq + n0 + tt] = aa;
            }
            __syncthreads();
        }
    }
    gsync();

    // ===== P3: 144 blocks = (batch, 4-chunk group):
    //   stage pm/ks/gxs; totals computed FROM SMEM (warps 0-3);
    //   k* searches on warps 4-7 (144*4 = 576 warp-items exactly) =============
    {
        float* gxs = (float*)SM;                   // [4][32][32] = 16384B
        float* ks  = (float*)(SM + 16384);         // [4][32] = 512B
        int*   pm  = (int*)(SM + 16896);           // [4][32] = 512B

        if (blockIdx.x < 144) {
            int b4 = blockIdx.x / 18;
            int cg0 = (blockIdx.x % 18) * 4;
            if (t < 128) {
                pm[t] = s_perm[b4*Nq + cg0*CHSZ + t];
                ks[t] = s_keys[b4*Nq + cg0*CHSZ + t];
            }
            __syncthreads();
            for (int idx = t; idx < 4*32*32; idx += NTHR) {
                int row = idx >> 5, i = idx & 31;
                gxs[idx] = s_gx[(b4*Nq + pm[row])*CIq + i];
            }
            __syncthreads();

            if (w < 4) {
                // chunk totals for own 4 chunks, straight from smem
                int q = w;
                float ag = 0.f, abg = 0.f;
                #pragma unroll 8
                for (int j = 0; j < 32; j++) {
                    float gg = gxs[(q*32 + j)*32 + lane];
                    float kk = ks[q*32 + j];
                    ag += gg;
                    abg = fmaf(kk, gg, abg);
                }
                s_ctg [(b4*NCH + cg0 + q)*CIq + lane] = ag;
                s_ctbg[(b4*NCH + cg0 + q)*CIq + lane] = abg;
            } else if (w < 8) {
                // fast k*: coarse boundary count + bulk chunk scan
                int idx = blockIdx.x*4 + (w - 4);  // 0..575
                int b = idx / NCH;
                int p = (idx % NCH)*32 + lane;
                float thr = -s_a[b*Nq + p];
                const float* keys = s_keys + b*Nq;
                float bnd0 = keys[lane*32 + 31];
                float bnd1 = keys[(lane + 32)*32 + 31];
                float bnd2 = (lane < 8) ? keys[(lane + 64)*32 + 31] : 3.4e38f;
                int ci = 0;
                #pragma unroll
                for (int l = 0; l < 32; l++)
                    ci += (__shfl_sync(0xffffffffu, bnd0, l) <= thr);
                #pragma unroll
                for (int l = 0; l < 32; l++)
                    ci += (__shfl_sync(0xffffffffu, bnd1, l) <= thr);
                #pragma unroll
                for (int l = 0; l < 8; l++)
                    ci += (__shfl_sync(0xffffffffu, bnd2, l) <= thr);
                int kst;
                if (ci >= NCH) {
                    kst = Nq;
                } else {
                    const float4* ck = (const float4*)(keys + ci*CHSZ);
                    int c2 = 0;
                    #pragma unroll
                    for (int q = 0; q < 8; q++) {
                        float4 v = ck[q];
                        c2 += (v.x <= thr) + (v.y <= thr) + (v.z <= thr) + (v.w <= thr);
                    }
                    kst = ci*CHSZ + c2;
                }
                s_kstar[b*Nq + p] = kst;
            } else if (blockIdx.x == 0) {
                // empty-suffix rows (warps 8-15 of block 0)
                if (w < 16 && (w - 8) < Bq) {
                    s_Sg [((w - 8)*NP1 + Nq)*CIq + lane] = 0.f;
                    s_Sbg[((w - 8)*NP1 + Nq)*CIq + lane] = 0.f;
                }
            }
        }
    }
    gsync();

    // ===== P4: suffix rows; gxs/pm/ks already resident; stage tg/tbg only =====
    if (blockIdx.x < 144) {
        float* gxs = (float*)SM;                   // persisted
        float* ks  = (float*)(SM + 16384);         // persisted
        float* tg  = (float*)(SM + 17408);         // [73][32] = 9344B
        float* tbg = (float*)(SM + 26752);         // [73][32]

        int b = blockIdx.x / 18;
        int cg0 = (blockIdx.x % 18) * 4;

        for (int idx = t; idx < 73*32; idx += NTHR) {
            float vg = 0.f, vbg = 0.f;
            if (idx < NCH*CIq) {
                vg  = s_ctg [b*NCH*CIq + idx];
                vbg = s_ctbg[b*NCH*CIq + idx];
            }
            tg[idx] = vg; tbg[idx] = vbg;
        }
        __syncthreads();

        if (t < 64) {
            float* p = (t >> 5) ? tbg : tg;
            int i = t & 31;
            float run = 0.f;
            for (int c = NCH - 1; c >= 0; c--) {
                run += p[c*32 + i];
                p[c*32 + i] = run;
            }
        }
        __syncthreads();

        {
            int q = w >> 2, hc = w & 3;
            int ch = cg0 + q;
            float rg  = tg [(ch + 1)*32 + lane];   // exclusive carry
            float rbg = tbg[(ch + 1)*32 + lane];
            int k0 = ch * CHSZ;
            int jstart = hc * 8;
            #pragma unroll
            for (int j = 31; j >= 0; j--) {
                if (j >= jstart) {
                    float gg = gxs[(q*32 + j)*32 + lane];
                    float kk = ks[q*32 + j];
                    rg += gg;
                    rbg = fmaf(kk, gg, rbg);
                    if (j < jstart + 8) {
                        s_Sg [(b*NP1 + k0 + j)*CIq + lane] = rg;
                        s_Sbg[(b*NP1 + k0 + j)*CIq + lane] = rbg;
                    }
                }
            }
        }
    }
    gsync();

    // ===== P5: y lookup + W projection + BN partials (pair of tiles/block) =====
    if (blockIdx.x < NTILE/2) {
        float* ws   = (float*)SM;                     // 64*33 = 8448B
        float* ys   = (float*)(SM + 8448);            // [2][64*36] = 18432B
        float* a_sm = (float*)(SM + 26880);           // [2][64]
        int*   k_sm = (int*)(SM + 27392);             // [2][64]
        float* psum = (float*)(SM + 27904);           // [2][4*64]
        float* psq  = (float*)(SM + 29952);           // [2][4*64]

        for (int idx = t; idx < Cq*CIq; idx += NTHR)
            ws[(idx >> 5)*33 + (idx & 31)] = W_w[idx];

        int half = t >> 8, tt = t & 255;
        float* ysh = ys + half*(64*36);
        int tile = blockIdx.x*2 + half;
        int b = tile / TILES, n0 = (tile % TILES)*64;

        if (tt < 64) {
            a_sm[half*64 + tt] = s_a[b*Nq + n0 + tt];
            k_sm[half*64 + tt] = s_kstar[b*Nq + n0 + tt];
        }
        __syncthreads();

        {
            int i = tt & 31, pg = tt >> 5;
            #pragma unroll
            for (int p = 0; p < 8; p++) {
                int pos = pg*8 + p;
                int k = k_sm[half*64 + pos];
                float sg  = s_Sg [(b*NP1 + k)*CIq + i];
                float sbg = s_Sbg[(b*NP1 + k)*CIq + i];
                ysh[pos*36 + i] = fmaf(a_sm[half*64 + pos], sg, sbg) * (1.0f / (float)Nq);
            }
        }
        __syncthreads();

        {
            int c = tt & 63, sub = tt >> 6;
            float wreg[CIq];
            #pragma unroll
            for (int i = 0; i < CIq; i++) wreg[i] = ws[c*33 + i];
            float wbc = W_b[c];
            float ls = 0.f, ls2 = 0.f;
            float* wyrow = s_wy + (b*Cq + c)*Nq + n0 + sub*16;
            #pragma unroll
            for (int q4 = 0; q4 < 4; q4++) {
                float av[4];
                #pragma unroll
                for (int u = 0; u < 4; u++) {
                    int pos = sub*16 + q4*4 + u;
                    const float4* yv = (const float4*)&ysh[pos*36];
                    float acc = 0.f;
                    #pragma unroll
                    for (int i4 = 0; i4 < CIq/4; i4++) {
                        float4 v = yv[i4];
                        acc = fmaf(wreg[i4*4+0], v.x, acc);
                        acc = fmaf(wreg[i4*4+1], v.y, acc);
                        acc = fmaf(wreg[i4*4+2], v.z, acc);
                        acc = fmaf(wreg[i4*4+3], v.w, acc);
                    }
                    av[u] = acc;
                    ls += acc; ls2 = fmaf(acc, acc, ls2);
                }
                float4 o;
                o.x = av[0] + wbc; o.y = av[1] + wbc;
                o.z = av[2] + wbc; o.w = av[3] + wbc;
                *(float4*)(wyrow + q4*4) = o;
            }
            psum[half*256 + sub*64 + c] = ls;
            psq [half*256 + sub*64 + c] = ls2;
        }
        __syncthreads();

        if (tt < 64) {
            int o = half*256;
            float s  = psum[o+tt] + psum[o+64+tt] + psum[o+128+tt] + psum[o+192+tt];
            float s2 = psq[o+tt]  + psq[o+64+tt]  + psq[o+128+tt]  + psq[o+192+tt];
            s_part[(tile*Cq + tt)*2 + 0] = s;
            s_part[(tile*Cq + tt)*2 + 1] = s2;
        }
    }
    gsync();

    // ========== P6: BN stats (redundant per block) + final ==========
    {
        float* red   = (float*)SM;            // [8][64]*2
        float* scale = (float*)(SM + 4096);   // 64
        float* shift = (float*)(SM + 4352);   // 64

        int c = t & 63, r = t >> 6;           // r: 0..7
        float s = 0.f, s2 = 0.f;
        const float2* pp = (const float2*)s_part;
        for (int blk = r; blk < NTILE; blk += 8) {
            float2 v = pp[blk*Cq + c];
            s += v.x; s2 += v.y;
        }
        red[r*64 + c] = s;
        red[512 + r*64 + c] = s2;
        __syncthreads();
        if (t < 64) {
            float ss = 0.f, qq = 0.f;
            #pragma unroll
            for (int rr = 0; rr < 8; rr++) {
                ss += red[rr*64 + t];
                qq += red[512 + rr*64 + t];
            }
            const float M = (float)(Bq * Nq);
            float mv = ss / M;
            float var = qq / M - mv*mv;
            float mean = W_b[t] + mv;
            float sc = bn_g[t] * rsqrtf(var + 1e-5f);
            scale[t] = sc;
            shift[t] = bn_b[t] - mean*sc;
        }
        __syncthreads();

        const int TOT4 = Bq*Cq*Nq/4;
        const float4* wy4 = (const float4*)s_wy;
        const float4* x4  = (const float4*)x;
        float4* o4 = (float4*)out;
        for (int i4 = blockIdx.x*NTHR + t; i4 < TOT4; i4 += GRID*NTHR) {
            int c2 = (i4 / (Nq/4)) & 63;
            float sc = scale[c2], sh = shift[c2];
            float4 ww = wy4[i4];
            float4 xv = x4[i4];
            float4 o;
            o.x = fmaf(ww.x, sc, sh) + xv.x;
            o.y = fmaf(ww.y, sc, sh) + xv.y;
            o.z = fmaf(ww.z, sc, sh) + xv.z;
            o.w = fmaf(ww.w, sc, sh) + xv.w;
            o4[i4] = o;
        }
    }
}

// ---------------- launch ----------------
extern "C" void kernel_launch(void* const* d_in, const int* in_sizes, int n_in,
                              void* d_out, int out_size) {
    const float* x     = (const float*)d_in[0];
    const float* g_w   = (const float*)d_in[1];
    const float* g_b   = (const float*)d_in[2];
    const float* th_w  = (const float*)d_in[3];
    const float* th_b  = (const float*)d_in[4];
    const float* ph_w  = (const float*)d_in[5];
    const float* ph_b  = (const float*)d_in[6];
    const float* cp_wt = (const float*)d_in[7];
    const float* cp_wp = (const float*)d_in[8];
    const float* W_w   = (const float*)d_in[9];
    const float* W_b   = (const float*)d_in[10];
    const float* bn_g  = (const float*)d_in[11];
    const float* bn_b  = (const float*)d_in[12];
    float* out = (float*)d_out;

    fused_nonlocal<<<GRID, NTHR>>>(x, g_w, g_b, th_w, th_b, ph_w, ph_b,
                                   cp_wt, cp_wp, W_w, W_b, bn_g, bn_b, out);
}